// round 16
// baseline (speedup 1.0000x reference)
#include <cuda_runtime.h>
#include <cuda_fp16.h>
#include <math_constants.h>
#include <cstdint>

// ---------------------------------------------------------------------------
// Problem constants
// ---------------------------------------------------------------------------
#define BATCH 2
#define SEQ   2048
#define DIM_  1024
#define HEADS 16
#define HDIM  64
#define FUT   2
#define MROWS (BATCH * SEQ)   // 4096
#define QKVN  (3 * DIM_)      // 3072
#define KDIM  1024

// GEMM tiling: 128x128 CTA tile, 8 warps of 32x64, 2 CTAs/SM
#define BM 128
#define BN 128
#define BK 64
#define NT (KDIM / BK)        // 16 k-tiles
#define NSTAGE 3
#define ROW_BYTES 128         // 64 halfs per row
#define A_STAGE_BYTES (BM * ROW_BYTES)              // 16384
#define B_STAGE_BYTES (BN * ROW_BYTES)              // 16384
#define STAGE_BYTES (A_STAGE_BYTES + B_STAGE_BYTES) // 32768
#define SMEM_BYTES (NSTAGE * STAGE_BYTES)           // 98304

#define MTILES (MROWS / BM)   // 32
#define NTILES1 (QKVN / BN)   // 24 n-tiles in GEMM1
#define G1_TILES (MTILES * NTILES1)   // 768
#define G1_GRID 296           // 2 CTAs/SM x 148 SMs, all co-resident

// job phase inside GEMM1: w_proj convert tiles, then attention jobs
#define WP_TILES 1024                 // w_proj 1024x1024 in 32x32 tiles
#define ATTN_JOBS (MTILES * HEADS)    // 512 (m-tile, head) jobs
#define TOTAL_JOBS (WP_TILES + ATTN_JOBS)

// front convert partition (256-thread blocks): x + w_qkv (+1 zeroing block)
#define XBLKS 4096            // x: 1,048,576 float4 / 256
#define WQBLKS (96 * 32)      // w_qkv: 3072x1024 in 32x32 tiles
#define CVT_BLOCKS (XBLKS + WQBLKS)

// ---------------------------------------------------------------------------
// Scratch (__device__ globals; allocation-free rule)
// ---------------------------------------------------------------------------
__device__ __half g_xh[(size_t)MROWS * KDIM];    // x fp16
__device__ __half g_wqt[(size_t)QKVN * KDIM];    // w_qkv^T fp16 [N][K]
__device__ __half g_wpt[(size_t)DIM_ * KDIM];    // w_proj^T fp16 [N][K]
__device__ __half g_qkv[(size_t)MROWS * QKVN];   // fp16 qkv (GEMM1 out)
__device__ __half g_ah[(size_t)MROWS * KDIM];    // attention out fp16
__device__ int    g_cnt[MTILES];                 // per-mtile n-tile completions
__device__ int    g_next_job;                    // job queue cursor

// ---------------------------------------------------------------------------
// async-copy / mma helpers
// ---------------------------------------------------------------------------
__device__ __forceinline__ void cp16(uint32_t sdst, const void* gsrc) {
    asm volatile("cp.async.cg.shared.global [%0], [%1], 16;\n" :: "r"(sdst), "l"(gsrc));
}
__device__ __forceinline__ void cp_commit() {
    asm volatile("cp.async.commit_group;\n" ::: "memory");
}
template <int N>
__device__ __forceinline__ void cp_wait() {
    asm volatile("cp.async.wait_group %0;\n" :: "n"(N) : "memory");
}
__device__ __forceinline__ void ldsm4(uint32_t& d0, uint32_t& d1, uint32_t& d2,
                                      uint32_t& d3, uint32_t addr) {
    asm volatile("ldmatrix.sync.aligned.m8n8.x4.shared.b16 {%0,%1,%2,%3}, [%4];"
                 : "=r"(d0), "=r"(d1), "=r"(d2), "=r"(d3) : "r"(addr));
}
__device__ __forceinline__ void mma16816(float* c, const uint32_t* a,
                                         uint32_t b0, uint32_t b1) {
    asm volatile("mma.sync.aligned.m16n8k16.row.col.f32.f16.f16.f32 "
                 "{%0,%1,%2,%3}, {%4,%5,%6,%7}, {%8,%9}, {%0,%1,%2,%3};"
                 : "+f"(c[0]), "+f"(c[1]), "+f"(c[2]), "+f"(c[3])
                 : "r"(a[0]), "r"(a[1]), "r"(a[2]), "r"(a[3]), "r"(b0), "r"(b1));
}

// ---------------------------------------------------------------------------
// GEMM1 fused: persistent qkv GEMM (fp16 out) + job phase
// (w_proj convert jobs + banded-attention jobs with counter readiness).
// ---------------------------------------------------------------------------
__global__ __launch_bounds__(256, 2)
void gemm1_fused_kernel(const __half* __restrict__ A,
                        const __half* __restrict__ B,
                        __half* __restrict__ C,         // qkv fp16
                        const float* __restrict__ w_proj,
                        __half* __restrict__ wpt,
                        __half* __restrict__ ah)
{
    extern __shared__ __align__(128) char sm[];
    const uint32_t sbase = (uint32_t)__cvta_generic_to_shared(sm);

    const int tid = threadIdx.x;
    const int wid = tid >> 5;
    const int lane = tid & 31;
    const int wm = (wid & 3) * 32;            // warp M offset (4 groups)
    const int wn = (wid >> 2) * 64;           // warp N offset (2 groups)

    const int lrow = lane & 15;
    const int lc = lane >> 4;
    const int l7 = lane & 7;
    const int erow = lane >> 2;
    const int ecol = (lane & 3) * 2;

#if __CUDA_ARCH__ >= 900
    cudaGridDependencySynchronize();          // wait for front converts
#endif

    // ===================== phase 1: persistent GEMM tiles ==================
    for (int tile = blockIdx.x; tile < G1_TILES; tile += G1_GRID) {
        const int m0 = (tile / NTILES1) * BM;  // m-major: an m-tile's 24
        const int n0 = (tile % NTILES1) * BN;  // n-tiles finish together

        float acc[2][8][4];
        #pragma unroll
        for (int i = 0; i < 2; i++)
            #pragma unroll
            for (int j = 0; j < 8; j++)
                #pragma unroll
                for (int e = 0; e < 4; e++)
                    acc[i][j][e] = 0.0f;

        auto load_tiles = [&](int kt, int s) {
            const int k0 = kt * BK;
            const uint32_t stA = sbase + s * STAGE_BYTES;
            const uint32_t stB = stA + A_STAGE_BYTES;
            #pragma unroll
            for (int i = 0; i < 4; i++) {
                const int ch = tid + i * 256;
                const int row = ch >> 3, seg = ch & 7;
                const int ps = seg ^ (row & 7);
                cp16(stA + row * ROW_BYTES + ps * 16,
                     A + (size_t)(m0 + row) * KDIM + k0 + seg * 8);
            }
            #pragma unroll
            for (int i = 0; i < 4; i++) {
                const int ch = tid + i * 256;
                const int row = ch >> 3, seg = ch & 7;
                const int ps = seg ^ (row & 7);
                cp16(stB + row * ROW_BYTES + ps * 16,
                     B + (size_t)(n0 + row) * KDIM + k0 + seg * 8);
            }
            cp_commit();
        };

        load_tiles(0, 0);
        load_tiles(1, 1);

        #pragma unroll 1
        for (int kt = 0; kt < NT; kt++) {
            const int s = kt % NSTAGE;
            if (kt == NT - 1) cp_wait<0>(); else cp_wait<1>();
            __syncthreads();
            if (kt + 2 < NT) load_tiles(kt + 2, (kt + 2) % NSTAGE);

            const uint32_t stA = sbase + s * STAGE_BYTES;
            const uint32_t stB = stA + A_STAGE_BYTES;
            const uint32_t aRow = stA + (wm + lrow) * ROW_BYTES;
            const uint32_t bRow = stB + (wn + lrow) * ROW_BYTES;

            #pragma unroll
            for (int q = 0; q < 4; q++) {
                const uint32_t chunk = q * 2 + lc;
                const uint32_t poff = (chunk ^ l7) * 16;

                uint32_t a[2][4];
                ldsm4(a[0][0], a[0][1], a[0][2], a[0][3], aRow + poff);
                ldsm4(a[1][0], a[1][1], a[1][2], a[1][3],
                      aRow + 16 * ROW_BYTES + poff);

                uint32_t b[4][4];
                #pragma unroll
                for (int ni = 0; ni < 4; ni++)
                    ldsm4(b[ni][0], b[ni][1], b[ni][2], b[ni][3],
                          bRow + ni * 16 * ROW_BYTES + poff);

                #pragma unroll
                for (int mi = 0; mi < 2; mi++)
                    #pragma unroll
                    for (int j = 0; j < 8; j++) {
                        const int ni = j >> 1, hf = j & 1;
                        mma16816(acc[mi][j], a[mi], b[ni][hf], b[ni][hf + 2]);
                    }
            }
        }

        // epilogue: fp16 half2 stores into qkv
        #pragma unroll
        for (int j = 0; j < 8; j++) {
            const int col = n0 + wn + j * 8 + ecol;
            #pragma unroll
            for (int mi = 0; mi < 2; mi++) {
                const int r = m0 + wm + mi * 16 + erow;
                *(__half2*)(C + (size_t)r * QKVN + col) =
                    __floats2half2_rn(acc[mi][j][0], acc[mi][j][1]);
                *(__half2*)(C + (size_t)(r + 8) * QKVN + col) =
                    __floats2half2_rn(acc[mi][j][2], acc[mi][j][3]);
            }
        }
        __syncthreads();                       // smem reusable next tile
        __threadfence();                       // publish epilogue stores
        if (tid == 0) atomicAdd(&g_cnt[tile / NTILES1], 1);
    }

    // ===================== phase 2: job queue ==============================
    __shared__ int s_job;
    while (true) {
        __syncthreads();                       // guard s_job + smem reuse
        if (tid == 0) s_job = atomicAdd(&g_next_job, 1);
        __syncthreads();
        const int j = s_job;
        if (j >= TOTAL_JOBS) break;

        if (j < WP_TILES) {
            // ---- w_proj transpose-convert tile (no dependencies) ----
            float (*t)[33] = (float(*)[33])sm;
            const int nb = (j & 31) * 32;
            const int kb = (j >> 5) * 32;
            const int tx = tid & 31;
            const int ty = tid >> 5;           // 0..7
            #pragma unroll
            for (int i = 0; i < 32; i += 8)
                t[ty + i][tx] = w_proj[(size_t)(kb + ty + i) * DIM_ + nb + tx];
            __syncthreads();
            #pragma unroll
            for (int i = 0; i < 32; i += 8)
                wpt[(size_t)(nb + ty + i) * KDIM + kb + tx] =
                    __float2half_rn(t[tx][ty + i]);
        } else {
            // ---- attention job: (m-tile, head), 8 warps x 16 rows ----
            const int aj = j - WP_TILES;
            const int mt = aj >> 4;            // claimed in m order
            const int h  = aj & 15;

            if (tid == 0) {
                const bool needs_next = (mt & 15) != 15;  // batch boundary
                while (true) {
                    const int c0 = atomicAdd(&g_cnt[mt], 0);
                    const int c1 = needs_next
                                 ? atomicAdd(&g_cnt[mt + 1], 0) : NTILES1;
                    if (c0 >= NTILES1 && c1 >= NTILES1) break;
                    __nanosleep(128);
                }
                __threadfence();               // acquire qkv stores
            }
            __syncthreads();

            #pragma unroll 1
            for (int it = 0; it < 16; it++) {
                const int m = mt * BM + wid * 16 + it;
                const int t = m % SEQ;
                const int nk = min(FUT + 1, SEQ - t);
                const size_t base = (size_t)m * QKVN + h * HDIM + 2 * lane;
                const float2 q2 = __half22float2(*(const __half2*)(C + base));

                float s[FUT + 1];
                #pragma unroll
                for (int jj = 0; jj <= FUT; jj++) {
                    if (jj < nk) {
                        const size_t kb = (size_t)(m + jj) * QKVN + DIM_ +
                                          h * HDIM + 2 * lane;
                        const float2 k2 =
                            __half22float2(*(const __half2*)(C + kb));
                        float d = q2.x * k2.x + q2.y * k2.y;
                        #pragma unroll
                        for (int off = 16; off > 0; off >>= 1)
                            d += __shfl_xor_sync(0xffffffffu, d, off);
                        s[jj] = d * 0.125f;
                    } else {
                        s[jj] = -CUDART_INF_F;
                    }
                }

                float mx = s[0];
                #pragma unroll
                for (int jj = 1; jj <= FUT; jj++) mx = fmaxf(mx, s[jj]);

                float e[FUT + 1], denom = 0.0f;
                #pragma unroll
                for (int jj = 0; jj <= FUT; jj++) {
                    e[jj] = (jj < nk) ? __expf(s[jj] - mx) : 0.0f;
                    denom += e[jj];
                }
                const float inv = 1.0f / denom;

                float o0 = 0.0f, o1 = 0.0f;
                #pragma unroll
                for (int jj = 0; jj <= FUT; jj++) {
                    if (jj < nk) {
                        const float p = e[jj] * inv;
                        const size_t vb = (size_t)(m + jj) * QKVN + 2 * DIM_ +
                                          h * HDIM + 2 * lane;
                        const float2 v2 =
                            __half22float2(*(const __half2*)(C + vb));
                        o0 = fmaf(p, v2.x, o0);
                        o1 = fmaf(p, v2.y, o1);
                    }
                }

                const size_t ob = (size_t)m * KDIM + h * HDIM + 2 * lane;
                *(__half2*)(ah + ob) = __floats2half2_rn(o0, o1);
            }
        }
    }
}

// ---------------------------------------------------------------------------
// GEMM2: fp16 GEMM, fp32 out + bias (R13-proven).
// ---------------------------------------------------------------------------
__global__ __launch_bounds__(256, 2)
void gemm2_kernel(const __half* __restrict__ A,
                  const __half* __restrict__ B,
                  float* __restrict__ C,
                  const float* __restrict__ bias, int ldN)
{
    extern __shared__ __align__(128) char sm[];
    const uint32_t sbase = (uint32_t)__cvta_generic_to_shared(sm);

    const int tid = threadIdx.x;
    const int wid = tid >> 5;
    const int lane = tid & 31;
    const int n0 = blockIdx.x * BN;
    const int m0 = blockIdx.y * BM;
    const int wm = (wid & 3) * 32;
    const int wn = (wid >> 2) * 64;

    float acc[2][8][4];
    #pragma unroll
    for (int i = 0; i < 2; i++)
        #pragma unroll
        for (int j = 0; j < 8; j++)
            #pragma unroll
            for (int e = 0; e < 4; e++)
                acc[i][j][e] = 0.0f;

    auto load_tiles = [&](int kt, int s) {
        const int k0 = kt * BK;
        const uint32_t stA = sbase + s * STAGE_BYTES;
        const uint32_t stB = stA + A_STAGE_BYTES;
        #pragma unroll
        for (int i = 0; i < 4; i++) {
            const int ch = tid + i * 256;
            const int row = ch >> 3, seg = ch & 7;
            const int ps = seg ^ (row & 7);
            cp16(stA + row * ROW_BYTES + ps * 16,
                 A + (size_t)(m0 + row) * KDIM + k0 + seg * 8);
        }
        #pragma unroll
        for (int i = 0; i < 4; i++) {
            const int ch = tid + i * 256;
            const int row = ch >> 3, seg = ch & 7;
            const int ps = seg ^ (row & 7);
            cp16(stB + row * ROW_BYTES + ps * 16,
                 B + (size_t)(n0 + row) * KDIM + k0 + seg * 8);
        }
        cp_commit();
    };

    const int lrow = lane & 15;
    const int lc = lane >> 4;
    const int l7 = lane & 7;

#if __CUDA_ARCH__ >= 900
    cudaGridDependencySynchronize();
#endif

    load_tiles(0, 0);
    load_tiles(1, 1);

    #pragma unroll 1
    for (int kt = 0; kt < NT; kt++) {
        const int s = kt % NSTAGE;
        if (kt == NT - 1) cp_wait<0>(); else cp_wait<1>();
        __syncthreads();
        if (kt + 2 < NT) load_tiles(kt + 2, (kt + 2) % NSTAGE);

        const uint32_t stA = sbase + s * STAGE_BYTES;
        const uint32_t stB = stA + A_STAGE_BYTES;
        const uint32_t aRow = stA + (wm + lrow) * ROW_BYTES;
        const uint32_t bRow = stB + (wn + lrow) * ROW_BYTES;

        #pragma unroll
        for (int q = 0; q < 4; q++) {
            const uint32_t chunk = q * 2 + lc;
            const uint32_t poff = (chunk ^ l7) * 16;

            uint32_t a[2][4];
            ldsm4(a[0][0], a[0][1], a[0][2], a[0][3], aRow + poff);
            ldsm4(a[1][0], a[1][1], a[1][2], a[1][3], aRow + 16 * ROW_BYTES + poff);

            uint32_t b[4][4];
            #pragma unroll
            for (int ni = 0; ni < 4; ni++)
                ldsm4(b[ni][0], b[ni][1], b[ni][2], b[ni][3],
                      bRow + ni * 16 * ROW_BYTES + poff);

            #pragma unroll
            for (int mi = 0; mi < 2; mi++)
                #pragma unroll
                for (int j = 0; j < 8; j++) {
                    const int ni = j >> 1, hf = j & 1;
                    mma16816(acc[mi][j], a[mi], b[ni][hf], b[ni][hf + 2]);
                }
        }
    }

    const int erow = lane >> 2;
    const int ecol = (lane & 3) * 2;
    #pragma unroll
    for (int j = 0; j < 8; j++) {
        const int col = n0 + wn + j * 8 + ecol;
        const float bx = __ldg(bias + col);
        const float by = __ldg(bias + col + 1);
        #pragma unroll
        for (int mi = 0; mi < 2; mi++) {
            const int r = m0 + wm + mi * 16 + erow;
            float2 v0 = make_float2(acc[mi][j][0] + bx, acc[mi][j][1] + by);
            float2 v1 = make_float2(acc[mi][j][2] + bx, acc[mi][j][3] + by);
            *(float2*)(C + (size_t)r * ldN + col) = v0;
            *(float2*)(C + (size_t)(r + 8) * ldN + col) = v1;
        }
    }
}

// ---------------------------------------------------------------------------
// Front converts: x->fp16, w_qkv^T->fp16, plus one block zeroing counters.
// ---------------------------------------------------------------------------
__global__ __launch_bounds__(256)
void front_convert_kernel(const float* __restrict__ x,
                          const float* __restrict__ w_qkv,
                          __half* __restrict__ xh,
                          __half* __restrict__ wqt)
{
    const int b = blockIdx.x;
    const int tid = threadIdx.x;

    if (b == CVT_BLOCKS) {                     // zero job-phase state
        if (tid < MTILES) g_cnt[tid] = 0;
        if (tid == MTILES) g_next_job = 0;
        return;
    }

    if (b < XBLKS) {
        const int i = b * 256 + tid;
        const float4 v = ((const float4*)x)[i];
        __half2* d = (__half2*)xh + i * 2;
        d[0] = __floats2half2_rn(v.x, v.y);
        d[1] = __floats2half2_rn(v.z, v.w);
        return;
    }

    __shared__ float t[32][33];
    const int tx = tid & 31;
    const int ty = tid >> 5;
    const int tb = b - XBLKS;
    const int ntx = QKVN / 32;
    const int nb = (tb % ntx) * 32;
    const int kb = (tb / ntx) * 32;

    #pragma unroll
    for (int i = 0; i < 32; i += 8)
        t[ty + i][tx] = w_qkv[(size_t)(kb + ty + i) * QKVN + nb + tx];
    __syncthreads();
    #pragma unroll
    for (int i = 0; i < 32; i += 8)
        wqt[(size_t)(nb + ty + i) * KDIM + kb + tx] = __float2half_rn(t[tx][ty + i]);
}

// ---------------------------------------------------------------------------
// kernel_launch — front cvt -> GEMM1(fused attn+wproj) -> GEMM2, PDL chain
// ---------------------------------------------------------------------------
extern "C" void kernel_launch(void* const* d_in, const int* in_sizes, int n_in,
                              void* d_out, int out_size)
{
    const float* x      = (const float*)d_in[0];
    const float* w_qkv  = (const float*)d_in[1];
    const float* w_proj = (const float*)d_in[2];
    const float* b_proj = (const float*)d_in[3];
    float* out = (float*)d_out;

    __half *xh, *wqt, *wpt, *ah, *qkv;
    cudaGetSymbolAddress((void**)&xh, g_xh);
    cudaGetSymbolAddress((void**)&wqt, g_wqt);
    cudaGetSymbolAddress((void**)&wpt, g_wpt);
    cudaGetSymbolAddress((void**)&ah, g_ah);
    cudaGetSymbolAddress((void**)&qkv, g_qkv);

    static bool attr_done = false;
    if (!attr_done) {
        cudaFuncSetAttribute(gemm1_fused_kernel,
                             cudaFuncAttributeMaxDynamicSharedMemorySize, SMEM_BYTES);
        cudaFuncSetAttribute(gemm2_kernel,
                             cudaFuncAttributeMaxDynamicSharedMemorySize, SMEM_BYTES);
        attr_done = true;
    }

    cudaLaunchAttribute pdl[1];
    pdl[0].id = cudaLaunchAttributeProgrammaticStreamSerialization;
    pdl[0].val.programmaticStreamSerializationAllowed = 1;

    // 1) front converts + counter zeroing (chain head)
    front_convert_kernel<<<CVT_BLOCKS + 1, 256>>>(x, w_qkv, xh, wqt);

    // 2) GEMM1 fused: qkv GEMM + w_proj convert jobs + attention jobs  [PDL]
    {
        cudaLaunchConfig_t cfg = {};
        cfg.gridDim = dim3(G1_GRID);
        cfg.blockDim = dim3(256);
        cfg.dynamicSmemBytes = SMEM_BYTES;
        cfg.stream = 0;
        cfg.attrs = pdl;
        cfg.numAttrs = 1;
        cudaLaunchKernelEx(&cfg, gemm1_fused_kernel,
                           (const __half*)xh, (const __half*)wqt,
                           (__half*)qkv, w_proj, (__half*)wpt, (__half*)ah);
    }

    // 3) out = attn @ w_proj + b  (M=4096, N=1024, K=1024), fp32 out  [PDL]
    {
        cudaLaunchConfig_t cfg = {};
        cfg.gridDim = dim3(DIM_ / BN, MROWS / BM);
        cfg.blockDim = dim3(256);
        cfg.dynamicSmemBytes = SMEM_BYTES;
        cfg.stream = 0;
        cfg.attrs = pdl;
        cfg.numAttrs = 1;
        cudaLaunchKernelEx(&cfg, gemm2_kernel,
                           (const __half*)ah, (const __half*)wpt,
                           (float*)out, (const float*)b_proj, (int)DIM_);
    }
}

// round 17
// speedup vs baseline: 1.1370x; 1.1370x over previous
#include <cuda_runtime.h>
#include <cuda_fp16.h>
#include <math_constants.h>
#include <cstdint>

// ---------------------------------------------------------------------------
// Problem constants
// ---------------------------------------------------------------------------
#define BATCH 2
#define SEQ   2048
#define DIM_  1024
#define HEADS 16
#define HDIM  64
#define FUT   2
#define MROWS (BATCH * SEQ)   // 4096
#define QKVN  (3 * DIM_)      // 3072
#define KDIM  1024

// GEMM tiling: 128x128 CTA tile, 8 warps of 32x64, 2 CTAs/SM
#define BM 128
#define BN 128
#define BK 64
#define NT (KDIM / BK)        // 16 k-tiles
#define NSTAGE 3
#define ROW_BYTES 128         // 64 halfs per row
#define A_STAGE_BYTES (BM * ROW_BYTES)              // 16384
#define B_STAGE_BYTES (BN * ROW_BYTES)              // 16384
#define STAGE_BYTES (A_STAGE_BYTES + B_STAGE_BYTES) // 32768
#define SMEM_BYTES (NSTAGE * STAGE_BYTES)           // 98304

// front convert partition (256-thread blocks): x + w_qkv (K64xN32 tiles)
#define XBLKS 4096            // x: 1,048,576 float4 / 256
#define WQBLKS ((QKVN / 32) * (KDIM / 64))          // 1536
#define CVT_BLOCKS (XBLKS + WQBLKS)

// attention kernel: attention blocks + w_proj convert blocks (K64xN32)
#define ATTN_BLOCKS (MROWS * HEADS * 32 / 256)      // 8192
#define WPBLKS ((DIM_ / 32) * (KDIM / 64))          // 512
#define ATTN_GRID (ATTN_BLOCKS + WPBLKS)

// ---------------------------------------------------------------------------
// Scratch (__device__ globals; allocation-free rule)
// ---------------------------------------------------------------------------
__device__ __half g_xh[(size_t)MROWS * KDIM];    // x fp16
__device__ __half g_wqt[(size_t)QKVN * KDIM];    // w_qkv^T fp16 [N][K]
__device__ __half g_wpt[(size_t)DIM_ * KDIM];    // w_proj^T fp16 [N][K]
__device__ __half g_qkv[(size_t)MROWS * QKVN];   // fp16 qkv (GEMM1 out)
__device__ __half g_ah[(size_t)MROWS * KDIM];    // attention out fp16

// ---------------------------------------------------------------------------
// async-copy / mma helpers
// ---------------------------------------------------------------------------
__device__ __forceinline__ void cp16(uint32_t sdst, const void* gsrc) {
    asm volatile("cp.async.cg.shared.global [%0], [%1], 16;\n" :: "r"(sdst), "l"(gsrc));
}
__device__ __forceinline__ void cp_commit() {
    asm volatile("cp.async.commit_group;\n" ::: "memory");
}
template <int N>
__device__ __forceinline__ void cp_wait() {
    asm volatile("cp.async.wait_group %0;\n" :: "n"(N) : "memory");
}
__device__ __forceinline__ void ldsm4(uint32_t& d0, uint32_t& d1, uint32_t& d2,
                                      uint32_t& d3, uint32_t addr) {
    asm volatile("ldmatrix.sync.aligned.m8n8.x4.shared.b16 {%0,%1,%2,%3}, [%4];"
                 : "=r"(d0), "=r"(d1), "=r"(d2), "=r"(d3) : "r"(addr));
}
__device__ __forceinline__ void mma16816(float* c, const uint32_t* a,
                                         uint32_t b0, uint32_t b1) {
    asm volatile("mma.sync.aligned.m16n8k16.row.col.f32.f16.f16.f32 "
                 "{%0,%1,%2,%3}, {%4,%5,%6,%7}, {%8,%9}, {%0,%1,%2,%3};"
                 : "+f"(c[0]), "+f"(c[1]), "+f"(c[2]), "+f"(c[3])
                 : "r"(a[0]), "r"(a[1]), "r"(a[2]), "r"(a[3]), "r"(b0), "r"(b1));
}

// Wide-store transpose-convert of one K64xN32 tile:
// W[K][N] fp32 -> Wt[N][K] fp16. Each warp stores full 128B rows (half2/lane).
__device__ __forceinline__ void transpose_tile_64x32(
    const float* __restrict__ W, __half* __restrict__ Wt,
    int N, int kb, int nb, float (*t)[33], int tid)
{
    const int tx = tid & 31;          // n within tile
    const int ty = tid >> 5;          // 0..7
    #pragma unroll
    for (int i = 0; i < 64; i += 8)
        t[ty + i][tx] = W[(size_t)(kb + ty + i) * N + nb + tx];
    __syncthreads();
    // store: warp w handles n = w*4..w*4+3; lane covers k pair (2l, 2l+1)
    const int wwid = tid >> 5;
    const int lane = tid & 31;
    #pragma unroll
    for (int q = 0; q < 4; q++) {
        const int n = wwid * 4 + q;
        const __half2 v = __floats2half2_rn(t[2 * lane][n], t[2 * lane + 1][n]);
        *(__half2*)(Wt + (size_t)(nb + n) * KDIM + kb + 2 * lane) = v;
    }
}

// ---------------------------------------------------------------------------
// fp16 GEMM (R13-proven): C[BMxBN] = A[M,K] @ B[N,K]^T (+bias for float C).
// 256 threads = 8 warps of 32x64; 2 CTAs/SM; cp.async A and B; PDL sync.
// ---------------------------------------------------------------------------
template <typename CT>
__global__ __launch_bounds__(256, 2)
void gemm_fp16_kernel(const __half* __restrict__ A,
                      const __half* __restrict__ B,
                      CT* __restrict__ C,
                      const float* __restrict__ bias, int ldN)
{
    extern __shared__ __align__(128) char sm[];
    const uint32_t sbase = (uint32_t)__cvta_generic_to_shared(sm);

    const int tid = threadIdx.x;
    const int wid = tid >> 5;
    const int lane = tid & 31;
    const int n0 = blockIdx.x * BN;
    const int m0 = blockIdx.y * BM;
    const int wm = (wid & 3) * 32;            // warp M offset (4 groups)
    const int wn = (wid >> 2) * 64;           // warp N offset (2 groups)

    float acc[2][8][4];
    #pragma unroll
    for (int i = 0; i < 2; i++)
        #pragma unroll
        for (int j = 0; j < 8; j++)
            #pragma unroll
            for (int e = 0; e < 4; e++)
                acc[i][j][e] = 0.0f;

    // ---- gmem -> smem loader with XOR swizzle (16B chunk ^= row&7) ----
    auto load_tiles = [&](int kt, int s) {
        const int k0 = kt * BK;
        const uint32_t stA = sbase + s * STAGE_BYTES;
        const uint32_t stB = stA + A_STAGE_BYTES;
        #pragma unroll
        for (int i = 0; i < 4; i++) {
            const int ch = tid + i * 256;
            const int row = ch >> 3, seg = ch & 7;
            const int ps = seg ^ (row & 7);
            cp16(stA + row * ROW_BYTES + ps * 16,
                 A + (size_t)(m0 + row) * KDIM + k0 + seg * 8);
        }
        #pragma unroll
        for (int i = 0; i < 4; i++) {
            const int ch = tid + i * 256;
            const int row = ch >> 3, seg = ch & 7;
            const int ps = seg ^ (row & 7);
            cp16(stB + row * ROW_BYTES + ps * 16,
                 B + (size_t)(n0 + row) * KDIM + k0 + seg * 8);
        }
        cp_commit();
    };

    const int lrow = lane & 15;               // row within 16-row tile
    const int lc = lane >> 4;                 // k-chunk half (0/1)
    const int l7 = lane & 7;                  // swizzle key

#if __CUDA_ARCH__ >= 900
    // PDL: setup above overlaps upstream tail; wait before consuming input.
    cudaGridDependencySynchronize();
#endif

    load_tiles(0, 0);
    load_tiles(1, 1);

    #pragma unroll 1
    for (int kt = 0; kt < NT; kt++) {
        const int s = kt % NSTAGE;
        if (kt == NT - 1) cp_wait<0>(); else cp_wait<1>();
        __syncthreads();
        if (kt + 2 < NT) load_tiles(kt + 2, (kt + 2) % NSTAGE);

        const uint32_t stA = sbase + s * STAGE_BYTES;
        const uint32_t stB = stA + A_STAGE_BYTES;
        const uint32_t aRow = stA + (wm + lrow) * ROW_BYTES;
        const uint32_t bRow = stB + (wn + lrow) * ROW_BYTES;

        #pragma unroll
        for (int q = 0; q < 4; q++) {         // k16 steps within BK=64
            const uint32_t chunk = q * 2 + lc;
            const uint32_t poff = (chunk ^ l7) * 16;

            uint32_t a[2][4];
            ldsm4(a[0][0], a[0][1], a[0][2], a[0][3], aRow + poff);
            ldsm4(a[1][0], a[1][1], a[1][2], a[1][3], aRow + 16 * ROW_BYTES + poff);

            uint32_t b[4][4];
            #pragma unroll
            for (int ni = 0; ni < 4; ni++)
                ldsm4(b[ni][0], b[ni][1], b[ni][2], b[ni][3],
                      bRow + ni * 16 * ROW_BYTES + poff);

            #pragma unroll
            for (int mi = 0; mi < 2; mi++)
                #pragma unroll
                for (int j = 0; j < 8; j++) {
                    const int ni = j >> 1, hf = j & 1;
                    mma16816(acc[mi][j], a[mi], b[ni][hf], b[ni][hf + 2]);
                }
        }
    }

    // ---- epilogue ----
    const int erow = lane >> 2;               // 0..7
    const int ecol = (lane & 3) * 2;          // 0,2,4,6
    #pragma unroll
    for (int j = 0; j < 8; j++) {
        const int col = n0 + wn + j * 8 + ecol;
        if constexpr (sizeof(CT) == 2) {
            // fp16 output, no bias: packed half2 stores
            #pragma unroll
            for (int mi = 0; mi < 2; mi++) {
                const int r = m0 + wm + mi * 16 + erow;
                *(__half2*)((__half*)C + (size_t)r * ldN + col) =
                    __floats2half2_rn(acc[mi][j][0], acc[mi][j][1]);
                *(__half2*)((__half*)C + (size_t)(r + 8) * ldN + col) =
                    __floats2half2_rn(acc[mi][j][2], acc[mi][j][3]);
            }
        } else {
            float bx = 0.0f, by = 0.0f;
            if (bias) { bx = __ldg(bias + col); by = __ldg(bias + col + 1); }
            #pragma unroll
            for (int mi = 0; mi < 2; mi++) {
                const int r = m0 + wm + mi * 16 + erow;
                float2 v0 = make_float2(acc[mi][j][0] + bx, acc[mi][j][1] + by);
                float2 v1 = make_float2(acc[mi][j][2] + bx, acc[mi][j][3] + by);
                *(float2*)((float*)C + (size_t)r * ldN + col) = v0;
                *(float2*)((float*)C + (size_t)(r + 8) * ldN + col) = v1;
            }
        }
    }
}

// ---------------------------------------------------------------------------
// Front converts: x->fp16 and w_qkv^T->fp16 (wide-store K64xN32 tiles).
// ---------------------------------------------------------------------------
__global__ __launch_bounds__(256)
void front_convert_kernel(const float* __restrict__ x,
                          const float* __restrict__ w_qkv,
                          __half* __restrict__ xh,
                          __half* __restrict__ wqt)
{
    const int b = blockIdx.x;
    const int tid = threadIdx.x;

    if (b < XBLKS) {
        const int i = b * 256 + tid;
        const float4 v = ((const float4*)x)[i];
        __half2* d = (__half2*)xh + i * 2;
        d[0] = __floats2half2_rn(v.x, v.y);
        d[1] = __floats2half2_rn(v.z, v.w);
        return;
    }

    __shared__ float t[64][33];
    const int tb = b - XBLKS;
    const int ntx = QKVN / 32;                // 96 n-tiles
    const int nb = (tb % ntx) * 32;
    const int kb = (tb / ntx) * 64;
    transpose_tile_64x32(w_qkv, wqt, QKVN, kb, nb, t, tid);
}

// ---------------------------------------------------------------------------
// Banded attention + w_proj convert. Attention CTAs PDL-sync on GEMM1;
// w_proj-convert CTAs skip the sync (inputs only) and overlap GEMM1's tail.
// ---------------------------------------------------------------------------
__global__ __launch_bounds__(256)
void banded_attn_kernel(const __half* __restrict__ qkv,
                        __half* __restrict__ out,
                        const float* __restrict__ w_proj,
                        __half* __restrict__ wpt)
{
    if (blockIdx.x >= ATTN_BLOCKS) {
        // w_proj transpose-convert; no dependence on GEMM1 -> run immediately.
        __shared__ float t[64][33];
        const int tb = blockIdx.x - ATTN_BLOCKS;
        const int ntx = DIM_ / 32;            // 32 n-tiles
        const int nb = (tb % ntx) * 32;
        const int kb = (tb / ntx) * 64;
        transpose_tile_64x32(w_proj, wpt, DIM_, kb, nb, t, threadIdx.x);
        return;
    }

    const int gwarp = (blockIdx.x * blockDim.x + threadIdx.x) >> 5;
    const int lane  = threadIdx.x & 31;

    const int h = gwarp >> 12;            // gwarp / MROWS
    const int m = gwarp & (MROWS - 1);    // gwarp % MROWS
    const int t = m % SEQ;
    const int nk = min(FUT + 1, SEQ - t);
    const size_t base = (size_t)m * QKVN + h * HDIM + 2 * lane;

#if __CUDA_ARCH__ >= 900
    cudaGridDependencySynchronize();
#endif

    const float2 q2 = __half22float2(*(const __half2*)(qkv + base));

    float s[FUT + 1];
    #pragma unroll
    for (int j = 0; j <= FUT; j++) {
        if (j < nk) {
            const size_t kb = (size_t)(m + j) * QKVN + DIM_ + h * HDIM + 2 * lane;
            const float2 k2 = __half22float2(*(const __half2*)(qkv + kb));
            float d = q2.x * k2.x + q2.y * k2.y;
            #pragma unroll
            for (int off = 16; off > 0; off >>= 1)
                d += __shfl_xor_sync(0xffffffffu, d, off);
            s[j] = d * 0.125f;
        } else {
            s[j] = -CUDART_INF_F;
        }
    }

    float mx = s[0];
    #pragma unroll
    for (int j = 1; j <= FUT; j++) mx = fmaxf(mx, s[j]);

    float e[FUT + 1], denom = 0.0f;
    #pragma unroll
    for (int j = 0; j <= FUT; j++) {
        e[j] = (j < nk) ? __expf(s[j] - mx) : 0.0f;
        denom += e[j];
    }
    const float inv = 1.0f / denom;

    float o0 = 0.0f, o1 = 0.0f;
    #pragma unroll
    for (int j = 0; j <= FUT; j++) {
        if (j < nk) {
            const float p = e[j] * inv;
            const size_t vb = (size_t)(m + j) * QKVN + 2 * DIM_ + h * HDIM + 2 * lane;
            const float2 v2 = __half22float2(*(const __half2*)(qkv + vb));
            o0 = fmaf(p, v2.x, o0);
            o1 = fmaf(p, v2.y, o1);
        }
    }

    const size_t ob = (size_t)m * KDIM + h * HDIM + 2 * lane;
    *(__half2*)(out + ob) = __floats2half2_rn(o0, o1);
}

// ---------------------------------------------------------------------------
// kernel_launch — front cvt -> GEMM1 -> (attn + wproj cvt) -> GEMM2, PDL chain
// ---------------------------------------------------------------------------
extern "C" void kernel_launch(void* const* d_in, const int* in_sizes, int n_in,
                              void* d_out, int out_size)
{
    const float* x      = (const float*)d_in[0];
    const float* w_qkv  = (const float*)d_in[1];
    const float* w_proj = (const float*)d_in[2];
    const float* b_proj = (const float*)d_in[3];
    float* out = (float*)d_out;

    __half *xh, *wqt, *wpt, *ah, *qkv;
    cudaGetSymbolAddress((void**)&xh, g_xh);
    cudaGetSymbolAddress((void**)&wqt, g_wqt);
    cudaGetSymbolAddress((void**)&wpt, g_wpt);
    cudaGetSymbolAddress((void**)&ah, g_ah);
    cudaGetSymbolAddress((void**)&qkv, g_qkv);

    static bool attr_done = false;
    if (!attr_done) {
        cudaFuncSetAttribute(gemm_fp16_kernel<__half>,
                             cudaFuncAttributeMaxDynamicSharedMemorySize, SMEM_BYTES);
        cudaFuncSetAttribute(gemm_fp16_kernel<float>,
                             cudaFuncAttributeMaxDynamicSharedMemorySize, SMEM_BYTES);
        attr_done = true;
    }

    cudaLaunchAttribute pdl[1];
    pdl[0].id = cudaLaunchAttributeProgrammaticStreamSerialization;
    pdl[0].val.programmaticStreamSerializationAllowed = 1;

    // 1) front converts (x + w_qkv; chain head)
    front_convert_kernel<<<CVT_BLOCKS, 256>>>(x, w_qkv, xh, wqt);

    // 2) qkv = x @ w_qkv  (M=4096, N=3072, K=1024), fp16 out  [PDL]
    {
        cudaLaunchConfig_t cfg = {};
        cfg.gridDim = dim3(QKVN / BN, MROWS / BM);
        cfg.blockDim = dim3(256);
        cfg.dynamicSmemBytes = SMEM_BYTES;
        cfg.stream = 0;
        cfg.attrs = pdl;
        cfg.numAttrs = 1;
        cudaLaunchKernelEx(&cfg, gemm_fp16_kernel<__half>,
                           (const __half*)xh, (const __half*)wqt,
                           (__half*)qkv, (const float*)nullptr, (int)QKVN);
    }

    // 3) banded attention + w_proj convert  [PDL; cvt CTAs overlap GEMM1 tail]
    {
        cudaLaunchConfig_t cfg = {};
        cfg.gridDim = dim3(ATTN_GRID);
        cfg.blockDim = dim3(256);
        cfg.stream = 0;
        cfg.attrs = pdl;
        cfg.numAttrs = 1;
        cudaLaunchKernelEx(&cfg, banded_attn_kernel,
                           (const __half*)qkv, (__half*)ah, w_proj, (__half*)wpt);
    }

    // 4) out = attn @ w_proj + b  (M=4096, N=1024, K=1024), fp32 out  [PDL]
    {
        cudaLaunchConfig_t cfg = {};
        cfg.gridDim = dim3(DIM_ / BN, MROWS / BM);
        cfg.blockDim = dim3(256);
        cfg.dynamicSmemBytes = SMEM_BYTES;
        cfg.stream = 0;
        cfg.attrs = pdl;
        cfg.numAttrs = 1;
        cudaLaunchKernelEx(&cfg, gemm_fp16_kernel<float>,
                           (const __half*)ah, (const __half*)wpt,
                           (float*)out, (const float*)b_proj, (int)DIM_);
    }
}